// round 5
// baseline (speedup 1.0000x reference)
#include <cuda_runtime.h>
#include <cstdint>

#define EDGES 625000
#define DD    128
#define BE    64
#define NT    256
#define NCTA  ((EDGES + BE - 1) / BE)   // 9766

// ---------------- smem layout (bytes) ----------------
// A buf: 16 blocks x 528B = 8448 ; x2
// B buf: 4 ksteps x 16 ntiles x 256B = 16384 ; x3 ring
// H frag: 64 blocks x 528B = 33792
#define SM_A0   0
#define SM_A1   8448
#define SM_B0   16896
#define SM_B1   33280
#define SM_B2   49664
#define SM_H    66048
#define SM_P    99840
#define P_B1    (SM_P + 0)
#define P_B2    (SM_P + 512)
#define P_G     (SM_P + 1024)
#define P_BT    (SM_P + 1536)
#define P_SEND  (SM_P + 2048)
#define P_RECV  (SM_P + 2304)
#define SM_HOUT 0                       // 64 x 132 f32 = 33792, overlays A/B0 post-GEMM2
#define SMEM_ALLOC 102400               // x2 CTAs = 200KB <= 227KB

// weights in tf32 fragment layout: [kstep][ntile(16)][lane(32)][reg(2)]
__device__ __align__(16) float g_W1F[48 * 16 * 64];
__device__ __align__(16) float g_W2F[16 * 16 * 64];

__device__ __forceinline__ uint32_t f2tf32(float x) {
    uint32_t u;
    asm("cvt.rna.tf32.f32 %0, %1;" : "=r"(u) : "f"(x));
    return u;
}

__global__ void prep_w_kernel(const float* __restrict__ W1,
                              const float* __restrict__ W2) {
    int i = blockIdx.x * 256 + threadIdx.x;
    if (i < 384 * 128) {
        int k = i >> 7, n = i & 127;
        int ks = k >> 3, nt = n >> 3;
        int lane = (n & 7) * 4 + (k & 3);
        int reg  = (k & 7) >> 2;
        g_W1F[(ks * 16 + nt) * 64 + lane * 2 + reg] = __uint_as_float(f2tf32(W1[i]));
    }
    if (i < 128 * 128) {
        int k = i >> 7, n = i & 127;
        int ks = k >> 3, nt = n >> 3;
        int lane = (n & 7) * 4 + (k & 3);
        int reg  = (k & 7) >> 2;
        g_W2F[(ks * 16 + nt) * 64 + lane * 2 + reg] = __uint_as_float(f2tf32(W2[i]));
    }
}

__device__ __forceinline__ void mma_tf32(float& c0, float& c1, float& c2, float& c3,
                                         uint32_t a0, uint32_t a1, uint32_t a2, uint32_t a3,
                                         uint32_t b0, uint32_t b1) {
    asm volatile("mma.sync.aligned.m16n8k8.row.col.f32.tf32.tf32.f32 "
                 "{%0,%1,%2,%3}, {%4,%5,%6,%7}, {%8,%9}, {%0,%1,%2,%3};"
                 : "+f"(c0), "+f"(c1), "+f"(c2), "+f"(c3)
                 : "r"(a0), "r"(a1), "r"(a2), "r"(a3), "r"(b0), "r"(b1));
}

__device__ __forceinline__ void cp16(uint32_t saddr, const void* gptr) {
    asm volatile("cp.async.cg.shared.global [%0], [%1], 16;"
                 :: "r"(saddr), "l"(gptr));
}
#define CP_COMMIT() asm volatile("cp.async.commit_group;" ::: "memory")
#define CP_WAIT(n)  asm volatile("cp.async.wait_group %0;" :: "n"(n) : "memory")

// B subchunk j (k32): 0..11 -> W1F, 12..15 -> W2F
__device__ __forceinline__ const float* bsrc(int j) {
    return (j < 12) ? (g_W1F + j * 4096) : (g_W2F + (j - 12) * 4096);
}

__global__ __launch_bounds__(NT, 2) void edge_mlp_mma(
    const float* __restrict__ node_attr,
    const void*  __restrict__ eidx_raw,
    const float* __restrict__ edge_attr,
    const float* __restrict__ b1g,
    const float* __restrict__ b2g,
    const float* __restrict__ gg,
    const float* __restrict__ btg,
    float* __restrict__ out)
{
    extern __shared__ char smem[];
    uint32_t smb;
    asm("{ .reg .u64 t; cvta.to.shared.u64 t, %1; cvt.u32.u64 %0, t; }"
        : "=r"(smb) : "l"(smem));

    const int tid  = threadIdx.x;
    const int wid  = tid >> 5;
    const int lane = tid & 31;
    const int g    = lane >> 2;
    const int t    = lane & 3;
    const int wm   = wid >> 2;     // 0..1 (M half, 32 rows)
    const int wn   = wid & 3;      // 0..3 (N quarter, 32 cols)
    const int e0   = blockIdx.x * BE;

    if (tid < 128) {
        ((float*)(smem + P_B1))[tid] = b1g[tid];
        ((float*)(smem + P_B2))[tid] = b2g[tid];
        ((float*)(smem + P_G ))[tid] = gg[tid];
        ((float*)(smem + P_BT))[tid] = btg[tid];
    }
    const int* raw32 = (const int*)eidx_raw;
    bool is64 = true;
    #pragma unroll
    for (int i = 0; i < 16; i++) is64 &= (raw32[2 * i + 1] == 0);
    if (tid < BE) {
        int eg = e0 + tid; if (eg >= EDGES) eg = EDGES - 1;
        int s, r;
        if (is64) { const long long* p = (const long long*)eidx_raw;
                    s = (int)p[eg]; r = (int)p[EDGES + eg]; }
        else      { s = raw32[eg]; r = raw32[EDGES + eg]; }
        ((int*)(smem + P_SEND))[tid] = s;
        ((int*)(smem + P_RECV))[tid] = r;
    }

    const uint32_t bbase[3] = {smb + SM_B0, smb + SM_B1, smb + SM_B2};
    const uint32_t boff[3]  = {SM_B0, SM_B1, SM_B2};

    // issue B(0), B(1) as two groups
    #pragma unroll
    for (int j0 = 0; j0 < 2; j0++) {
        #pragma unroll
        for (int it = 0; it < 4; it++) {
            int idx = tid + it * NT;           // 0..1023 16B slots
            cp16(bbase[j0] + idx * 16, bsrc(j0) + idx * 4);
        }
        CP_COMMIT();
    }
    __syncthreads();   // send/recv visible

    const int* sSend = (const int*)(smem + P_SEND);
    const int* sRecv = (const int*)(smem + P_RECV);

    // prefetch A chunk 0 (sender, k 0..31)
    float4 prA[2];
    #pragma unroll
    for (int it = 0; it < 2; it++) {
        int idx = tid + it * NT;               // 0..511 float4 slots
        int row = idx >> 3, jc = idx & 7;
        prA[it] = *(const float4*)(node_attr + (size_t)sSend[row] * DD + jc * 4);
    }

    float acc[2][4][4];
    #pragma unroll
    for (int i = 0; i < 2; i++)
        #pragma unroll
        for (int j = 0; j < 4; j++)
            #pragma unroll
            for (int r = 0; r < 4; r++) acc[i][j][r] = 0.0f;

    // =================== GEMM1: 12 chunks of k=32 ===================
    #pragma unroll 1
    for (int c = 0; c < 12; c++) {
        const char* abuf = smem + ((c & 1) ? SM_A1 : SM_A0);
        // scatter A(c) -> frag layout (tf32)
        #pragma unroll
        for (int it = 0; it < 2; it++) {
            int idx = tid + it * NT;
            int row = idx >> 3, jc = idx & 7;
            int blk  = (row >> 4) * 4 + (jc >> 1);
            int rbit = (row >> 3) & 1;
            int lo2  = 2 * (jc & 1);
            uint32_t* dst = (uint32_t*)(abuf + blk * 528) + (row & 7) * 16;
            const float* v = &prA[it].x;
            #pragma unroll
            for (int s4 = 0; s4 < 4; s4++)
                dst[s4 * 4 + lo2 + rbit] = f2tf32(v[s4]);
        }
        CP_WAIT(1);              // B(c) landed (B(c+1) may be in flight)
        __syncthreads();         // A(c) visible; MMA(c-1) done by all warps

        {   // issue B(c+2) into ring slot (c+2)%3
            int jn = c + 2;
            uint32_t dstb = bbase[jn % 3];
            const float* src = bsrc(jn);
            #pragma unroll
            for (int it = 0; it < 4; it++) {
                int idx = tid + it * NT;
                cp16(dstb + idx * 16, src + idx * 4);
            }
            CP_COMMIT();
        }
        if (c < 11) {            // LDG A(c+1)
            int cn = c + 1;
            #pragma unroll
            for (int it = 0; it < 2; it++) {
                int idx = tid + it * NT;
                int row = idx >> 3, jc = idx & 7;
                const float* src;
                if (cn < 4)      src = node_attr + (size_t)sSend[row] * DD + cn * 32;
                else if (cn < 8) src = node_attr + (size_t)sRecv[row] * DD + (cn - 4) * 32;
                else { int eg = e0 + row; if (eg >= EDGES) eg = EDGES - 1;
                       src = edge_attr + (size_t)eg * DD + (cn - 8) * 32; }
                prA[it] = *(const float4*)(src + jc * 4);
            }
        }

        const char* bb = smem + boff[c % 3];
        #pragma unroll
        for (int s = 0; s < 4; s++) {
            uint2 b[4];
            #pragma unroll
            for (int j = 0; j < 4; j++)
                b[j] = *(const uint2*)(bb + ((s * 16) + wn * 4 + j) * 256 + lane * 8);
            #pragma unroll
            for (int i = 0; i < 2; i++) {
                uint4 a = *(const uint4*)(abuf + ((wm * 2 + i) * 4 + s) * 528 + lane * 16);
                #pragma unroll
                for (int j = 0; j < 4; j++)
                    mma_tf32(acc[i][j][0], acc[i][j][1], acc[i][j][2], acc[i][j][3],
                             a.x, a.y, a.z, a.w, b[j].x, b[j].y);
            }
        }
    }

    // ========== epilogue1: bias + ReLU + tf32 -> H frag ==========
    {
        const float* B1 = (const float*)(smem + P_B1);
        #pragma unroll
        for (int i = 0; i < 2; i++) {
            int mtb = wm * 2 + i;
            #pragma unroll
            for (int j = 0; j < 4; j++) {
                int ks2 = wn * 4 + j;
                uint32_t* blkp = (uint32_t*)(smem + SM_H + (mtb * 16 + ks2) * 528);
                #pragma unroll
                for (int r = 0; r < 4; r++) {
                    int col = wn * 32 + j * 8 + 2 * t + (r & 1);
                    float x = fmaxf(acc[i][j][r] + B1[col], 0.0f);
                    int kl = 2 * t + (r & 1);
                    blkp[g * 16 + (kl & 3) * 4 + 2 * (kl >> 2) + (r >> 1)] = f2tf32(x);
                    acc[i][j][r] = 0.0f;
                }
            }
        }
    }
    __syncthreads();   // H complete

    // =================== GEMM2: 4 chunks of k=32 (B stream j=12..15) ===================
    #pragma unroll 1
    for (int c2 = 0; c2 < 4; c2++) {
        int jg = 12 + c2;
        if (c2 < 3) { CP_WAIT(1); } else { CP_WAIT(0); }
        __syncthreads();          // prior MMA done by all before ring-slot reuse
        if (jg + 2 <= 15) {
            uint32_t dstb = bbase[(jg + 2) % 3];
            const float* src = bsrc(jg + 2);
            #pragma unroll
            for (int it = 0; it < 4; it++) {
                int idx = tid + it * NT;
                cp16(dstb + idx * 16, src + idx * 4);
            }
            CP_COMMIT();
        }
        const char* bb = smem + boff[jg % 3];
        #pragma unroll
        for (int s = 0; s < 4; s++) {
            uint2 b[4];
            #pragma unroll
            for (int j = 0; j < 4; j++)
                b[j] = *(const uint2*)(bb + ((s * 16) + wn * 4 + j) * 256 + lane * 8);
            #pragma unroll
            for (int i = 0; i < 2; i++) {
                uint4 a = *(const uint4*)(smem + SM_H +
                          ((wm * 2 + i) * 16 + (c2 * 4 + s)) * 528 + lane * 16);
                #pragma unroll
                for (int j = 0; j < 4; j++)
                    mma_tf32(acc[i][j][0], acc[i][j][1], acc[i][j][2], acc[i][j][3],
                             a.x, a.y, a.z, a.w, b[j].x, b[j].y);
            }
        }
    }
    __syncthreads();   // all GEMM2 reads done before Hout overlays A/B0

    // ========== epilogue2: bias2 -> Hout (natural layout) ==========
    {
        const float* B2 = (const float*)(smem + P_B2);
        float* Ho = (float*)(smem + SM_HOUT);
        #pragma unroll
        for (int i = 0; i < 2; i++) {
            #pragma unroll
            for (int j = 0; j < 4; j++) {
                #pragma unroll
                for (int r = 0; r < 4; r++) {
                    int row = wm * 32 + i * 16 + g + 8 * (r >> 1);
                    int col = wn * 32 + j * 8 + 2 * t + (r & 1);
                    Ho[row * 132 + col] = acc[i][j][r] + B2[col];
                }
            }
        }
    }
    __syncthreads();

    // ========== LayerNorm + store ==========
    {
        const float* Ho = (const float*)(smem + SM_HOUT);
        const float* G  = (const float*)(smem + P_G);
        const float* Bt = (const float*)(smem + P_BT);
        float g0 = G[lane],      g1 = G[lane + 32],  g2 = G[lane + 64],  g3 = G[lane + 96];
        float b0 = Bt[lane],     b1 = Bt[lane + 32], b2 = Bt[lane + 64], b3 = Bt[lane + 96];
        #pragma unroll 1
        for (int k = 0; k < 8; k++) {
            int row = wid * 8 + k;
            float v0 = Ho[row * 132 + lane];
            float v1 = Ho[row * 132 + lane + 32];
            float v2 = Ho[row * 132 + lane + 64];
            float v3 = Ho[row * 132 + lane + 96];
            float sum = v0 + v1 + v2 + v3;
            float sq  = v0 * v0 + v1 * v1 + v2 * v2 + v3 * v3;
            #pragma unroll
            for (int off = 16; off > 0; off >>= 1) {
                sum += __shfl_xor_sync(0xffffffffu, sum, off);
                sq  += __shfl_xor_sync(0xffffffffu, sq,  off);
            }
            float mu  = sum * (1.0f / 128.0f);
            float var = sq * (1.0f / 128.0f) - mu * mu;
            float rs  = rsqrtf(var + 1e-5f);
            int eg = e0 + row;
            if (eg < EDGES) {
                float* o = out + (size_t)eg * DD;
                o[lane]      = (v0 - mu) * rs * g0 + b0;
                o[lane + 32] = (v1 - mu) * rs * g1 + b1;
                o[lane + 64] = (v2 - mu) * rs * g2 + b2;
                o[lane + 96] = (v3 - mu) * rs * g3 + b3;
            }
        }
    }
}

extern "C" void kernel_launch(void* const* d_in, const int* in_sizes, int n_in,
                              void* d_out, int out_size) {
    const float* node_attr = (const float*)d_in[0];
    const void*  eidx      = d_in[1];
    const float* edge_attr = (const float*)d_in[2];
    const float* W1        = (const float*)d_in[3];
    const float* b1        = (const float*)d_in[4];
    const float* W2        = (const float*)d_in[5];
    const float* b2        = (const float*)d_in[6];
    const float* gamma_    = (const float*)d_in[7];
    const float* beta_     = (const float*)d_in[8];

    cudaFuncSetAttribute(edge_mlp_mma, cudaFuncAttributeMaxDynamicSharedMemorySize, SMEM_ALLOC);

    prep_w_kernel<<<192, 256>>>(W1, W2);
    edge_mlp_mma<<<NCTA, NT, SMEM_ALLOC>>>(node_attr, eidx, edge_attr,
                                           b1, b2, gamma_, beta_, (float*)d_out);
}

// round 6
// speedup vs baseline: 1.6390x; 1.6390x over previous
#include <cuda_runtime.h>
#include <cstdint>

#define EDGES 625000
#define DD    128
#define BE    128
#define NT    512
#define NCTA  ((EDGES + BE - 1) / BE)   // 4883

// ---------------- smem layout (bytes) ----------------
// A chunk (k64): 8 mblk x 4 kstep blocks x 512B = 16384 ; x2
// B chunk (k64): 4 kstep x 16 ntile blocks x 256B = 16384 ; x2
// H frag: 8 mblk x 8 kstep x 512B = 32768
#define SM_A0   0
#define SM_A1   16384
#define SM_B0   32768
#define SM_B1   49152
#define SM_H    65536
#define SM_P    98304
#define P_B1    (SM_P + 0)
#define P_B2    (SM_P + 512)
#define P_G     (SM_P + 1024)
#define P_BT    (SM_P + 1536)
#define P_SEND  (SM_P + 2048)
#define P_RECV  (SM_P + 2560)
#define SM_HOUT 0                       // 128 x 132 f32 = 67584, overlays A/B (+2KB of H) post-GEMM2
#define SMEM_ALLOC 102400

// weights in fp16 m16n8k16 B-fragment layout:
// block(kstep16, ntile8) = 256B: uint32 slot = lane*2 + r ; lane=(g<<2)|t
//   slot lo/hi = W[k][n], W[k+1][n]  with k = ks*16 + r*8 + t*2 , n = nt*8 + g
__device__ __align__(16) uint32_t g_W1F[24 * 16 * 64];   // 384/16 ksteps
__device__ __align__(16) uint32_t g_W2F[8 * 16 * 64];    // 128/16 ksteps

__device__ __forceinline__ uint32_t packf16(float lo, float hi) {
    uint32_t u;
    asm("cvt.rn.f16x2.f32 %0, %1, %2;" : "=r"(u) : "f"(hi), "f"(lo));
    return u;
}

__global__ void prep_w_kernel(const float* __restrict__ W1,
                              const float* __restrict__ W2) {
    int i = blockIdx.x * 256 + threadIdx.x;          // grid covers 24576
    if (i < 24 * 16 * 64) {
        int blk = i >> 6, w = i & 63;
        int lane = w >> 1, r = w & 1;
        int g = lane >> 2, t = lane & 3;
        int ks = blk >> 4, nt = blk & 15;
        int k = ks * 16 + r * 8 + t * 2;
        int n = nt * 8 + g;
        g_W1F[i] = packf16(W1[k * 128 + n], W1[(k + 1) * 128 + n]);
    }
    if (i < 8 * 16 * 64) {
        int blk = i >> 6, w = i & 63;
        int lane = w >> 1, r = w & 1;
        int g = lane >> 2, t = lane & 3;
        int ks = blk >> 4, nt = blk & 15;
        int k = ks * 16 + r * 8 + t * 2;
        int n = nt * 8 + g;
        g_W2F[i] = packf16(W2[k * 128 + n], W2[(k + 1) * 128 + n]);
    }
}

__device__ __forceinline__ void mma_fp16(float& c0, float& c1, float& c2, float& c3,
                                         uint32_t a0, uint32_t a1, uint32_t a2, uint32_t a3,
                                         uint32_t b0, uint32_t b1) {
    asm volatile("mma.sync.aligned.m16n8k16.row.col.f32.f16.f16.f32 "
                 "{%0,%1,%2,%3}, {%4,%5,%6,%7}, {%8,%9}, {%0,%1,%2,%3};"
                 : "+f"(c0), "+f"(c1), "+f"(c2), "+f"(c3)
                 : "r"(a0), "r"(a1), "r"(a2), "r"(a3), "r"(b0), "r"(b1));
}

__device__ __forceinline__ void cp16(uint32_t saddr, const void* gptr) {
    asm volatile("cp.async.cg.shared.global [%0], [%1], 16;"
                 :: "r"(saddr), "l"(gptr));
}
#define CP_COMMIT() asm volatile("cp.async.commit_group;" ::: "memory")
#define CP_WAIT(n)  asm volatile("cp.async.wait_group %0;" :: "n"(n) : "memory")

__global__ __launch_bounds__(NT, 1) void edge_mlp_mma(
    const float* __restrict__ node_attr,
    const void*  __restrict__ eidx_raw,
    const float* __restrict__ edge_attr,
    const float* __restrict__ b1g,
    const float* __restrict__ b2g,
    const float* __restrict__ gg,
    const float* __restrict__ btg,
    float* __restrict__ out)
{
    extern __shared__ char smem[];
    uint32_t smb;
    asm("{ .reg .u64 t; cvta.to.shared.u64 t, %1; cvt.u32.u64 %0, t; }"
        : "=r"(smb) : "l"(smem));

    const int tid  = threadIdx.x;
    const int wid  = tid >> 5;
    const int lane = tid & 31;
    const int g    = lane >> 2;
    const int t    = lane & 3;
    const int wm   = wid >> 2;     // 0..3 (M quarter, 32 rows)
    const int wn   = wid & 3;      // 0..3 (N quarter, 32 cols)
    const int e0   = blockIdx.x * BE;

    if (tid < 128) {
        ((float*)(smem + P_B1))[tid] = b1g[tid];
        ((float*)(smem + P_B2))[tid] = b2g[tid];
        ((float*)(smem + P_G ))[tid] = gg[tid];
        ((float*)(smem + P_BT))[tid] = btg[tid];
    }
    const int* raw32 = (const int*)eidx_raw;
    bool is64 = true;
    #pragma unroll
    for (int i = 0; i < 16; i++) is64 &= (raw32[2 * i + 1] == 0);
    if (tid < BE) {
        int eg = e0 + tid; if (eg >= EDGES) eg = EDGES - 1;
        int s, r;
        if (is64) { const long long* p = (const long long*)eidx_raw;
                    s = (int)p[eg]; r = (int)p[EDGES + eg]; }
        else      { s = raw32[eg]; r = raw32[EDGES + eg]; }
        ((int*)(smem + P_SEND))[tid] = s;
        ((int*)(smem + P_RECV))[tid] = r;
    }

    const uint32_t bbuf[2] = {smb + SM_B0, smb + SM_B1};

    // issue B chunk 0 of GEMM1 (16KB, 1024 x 16B slots)
    #pragma unroll
    for (int it = 0; it < 2; it++) {
        int idx = tid + it * NT;
        cp16(bbuf[0] + idx * 16, g_W1F + idx * 4);
    }
    CP_COMMIT();
    __syncthreads();   // send/recv visible

    const int* sSend = (const int*)(smem + P_SEND);
    const int* sRecv = (const int*)(smem + P_RECV);

    // prefetch A chunk 0 (sender, k 0..63): 2048 float4 slots
    float4 prA[4];
    #pragma unroll
    for (int it = 0; it < 4; it++) {
        int idx = tid + it * NT;
        int row = idx >> 4, jc = idx & 15;
        prA[it] = *(const float4*)(node_attr + (size_t)sSend[row] * DD + jc * 4);
    }

    float acc[2][4][4];
    #pragma unroll
    for (int i = 0; i < 2; i++)
        #pragma unroll
        for (int j = 0; j < 4; j++)
            #pragma unroll
            for (int r = 0; r < 4; r++) acc[i][j][r] = 0.0f;

    // =================== GEMM1: 6 chunks of k=64 ===================
    #pragma unroll 1
    for (int c = 0; c < 6; c++) {
        const char* abuf = smem + ((c & 1) ? SM_A1 : SM_A0);
        // scatter A(c) -> fp16 fragment layout
        #pragma unroll
        for (int it = 0; it < 4; it++) {
            int idx = tid + it * NT;
            int row = idx >> 4, jc = idx & 15;          // float4 at cols 4jc..4jc+3
            int gg_ = row & 7, rbit = (row >> 3) & 1;
            int pp0 = (2 * jc) & 7;                      // colpair within kstep
            int t0  = pp0 & 3, hi = pp0 >> 2;
            int r   = rbit + 2 * hi;
            uint32_t* blkp = (uint32_t*)(abuf + (((row >> 4) * 4) + (jc >> 2)) * 512);
            int s0 = (gg_ * 4 + t0) * 4 + r;
            blkp[s0]     = packf16(prA[it].x, prA[it].y);
            blkp[s0 + 4] = packf16(prA[it].z, prA[it].w);   // next colpair -> lane+1
        }
        CP_WAIT(0);              // B(c) landed
        __syncthreads();         // A(c) visible; MMA(c-1) done by all warps

        if (c < 5) {
            int cn = c + 1;
            #pragma unroll
            for (int it = 0; it < 2; it++) {
                int idx = tid + it * NT;
                cp16(bbuf[cn & 1] + idx * 16, g_W1F + cn * 4096 + idx * 4);
            }
            CP_COMMIT();
            #pragma unroll
            for (int it = 0; it < 4; it++) {
                int idx = tid + it * NT;
                int row = idx >> 4, jc = idx & 15;
                const float* src;
                if (cn < 2)      src = node_attr + (size_t)sSend[row] * DD + cn * 64;
                else if (cn < 4) src = node_attr + (size_t)sRecv[row] * DD + (cn - 2) * 64;
                else { int eg = e0 + row; if (eg >= EDGES) eg = EDGES - 1;
                       src = edge_attr + (size_t)eg * DD + (cn - 4) * 64; }
                prA[it] = *(const float4*)(src + jc * 4);
            }
        }

        const char* bb = smem + (SM_B0 + (c & 1) * 16384);
        #pragma unroll
        for (int s = 0; s < 4; s++) {
            uint2 b[4];
            #pragma unroll
            for (int j = 0; j < 4; j++)
                b[j] = *(const uint2*)(bb + ((s * 16) + wn * 4 + j) * 256 + lane * 8);
            #pragma unroll
            for (int i = 0; i < 2; i++) {
                uint4 a = *(const uint4*)(abuf + ((wm * 2 + i) * 4 + s) * 512 + lane * 16);
                #pragma unroll
                for (int j = 0; j < 4; j++)
                    mma_fp16(acc[i][j][0], acc[i][j][1], acc[i][j][2], acc[i][j][3],
                             a.x, a.y, a.z, a.w, b[j].x, b[j].y);
            }
        }
    }

    // issue GEMM2 B chunk 0 into buf0 (last read was MMA chunk 4 -> free)
    #pragma unroll
    for (int it = 0; it < 2; it++) {
        int idx = tid + it * NT;
        cp16(bbuf[0] + idx * 16, g_W2F + idx * 4);
    }
    CP_COMMIT();

    // ========== epilogue1: bias + ReLU -> H (fp16 A-frag layout) ==========
    {
        const float* B1 = (const float*)(smem + P_B1);
        #pragma unroll
        for (int i = 0; i < 2; i++) {
            #pragma unroll
            for (int j = 0; j < 4; j++) {
                int col = wn * 32 + j * 8 + 2 * t;
                float x0 = fmaxf(acc[i][j][0] + B1[col],     0.0f);
                float x1 = fmaxf(acc[i][j][1] + B1[col + 1], 0.0f);
                float x2 = fmaxf(acc[i][j][2] + B1[col],     0.0f);
                float x3 = fmaxf(acc[i][j][3] + B1[col + 1], 0.0f);
                uint32_t* blkp = (uint32_t*)(smem + SM_H +
                                 ((wm * 2 + i) * 8 + wn * 2 + (j >> 1)) * 512);
                int base = (g * 4 + t) * 4 + 2 * (j & 1);
                blkp[base]     = packf16(x0, x1);    // rows g
                blkp[base + 1] = packf16(x2, x3);    // rows g+8
                acc[i][j][0] = 0.0f; acc[i][j][1] = 0.0f;
                acc[i][j][2] = 0.0f; acc[i][j][3] = 0.0f;
            }
        }
    }
    __syncthreads();   // H complete; MMA1(5) done -> buf1 free

    // issue GEMM2 B chunk 1 into buf1
    #pragma unroll
    for (int it = 0; it < 2; it++) {
        int idx = tid + it * NT;
        cp16(bbuf[1] + idx * 16, g_W2F + 4096 + idx * 4);
    }
    CP_COMMIT();
    CP_WAIT(1);        // B2(0) done, B2(1) in flight
    __syncthreads();

    // =================== GEMM2: 2 chunks of k=64 ===================
    #pragma unroll 1
    for (int c = 0; c < 2; c++) {
        if (c == 1) { CP_WAIT(0); __syncthreads(); }
        const char* bb = smem + (SM_B0 + c * 16384);
        #pragma unroll
        for (int s = 0; s < 4; s++) {
            uint2 b[4];
            #pragma unroll
            for (int j = 0; j < 4; j++)
                b[j] = *(const uint2*)(bb + ((s * 16) + wn * 4 + j) * 256 + lane * 8);
            #pragma unroll
            for (int i = 0; i < 2; i++) {
                uint4 a = *(const uint4*)(smem + SM_H +
                          ((wm * 2 + i) * 8 + (c * 4 + s)) * 512 + lane * 16);
                #pragma unroll
                for (int j = 0; j < 4; j++)
                    mma_fp16(acc[i][j][0], acc[i][j][1], acc[i][j][2], acc[i][j][3],
                             a.x, a.y, a.z, a.w, b[j].x, b[j].y);
            }
        }
    }
    __syncthreads();   // all GEMM2 reads done before Hout overlays A/B/H

    // ========== epilogue2: bias2 -> Hout (natural layout) ==========
    {
        const float* B2 = (const float*)(smem + P_B2);
        float* Ho = (float*)(smem + SM_HOUT);
        #pragma unroll
        for (int i = 0; i < 2; i++) {
            #pragma unroll
            for (int j = 0; j < 4; j++) {
                #pragma unroll
                for (int r = 0; r < 4; r++) {
                    int row = wm * 32 + i * 16 + g + 8 * (r >> 1);
                    int col = wn * 32 + j * 8 + 2 * t + (r & 1);
                    Ho[row * 132 + col] = acc[i][j][r] + B2[col];
                }
            }
        }
    }
    __syncthreads();

    // ========== LayerNorm + store ==========
    {
        const float* Ho = (const float*)(smem + SM_HOUT);
        const float* G  = (const float*)(smem + P_G);
        const float* Bt = (const float*)(smem + P_BT);
        float g0 = G[lane],      g1 = G[lane + 32],  g2 = G[lane + 64],  g3 = G[lane + 96];
        float b0 = Bt[lane],     b1 = Bt[lane + 32], b2 = Bt[lane + 64], b3 = Bt[lane + 96];
        #pragma unroll 1
        for (int k = 0; k < 8; k++) {
            int row = wid * 8 + k;
            float v0 = Ho[row * 132 + lane];
            float v1 = Ho[row * 132 + lane + 32];
            float v2 = Ho[row * 132 + lane + 64];
            float v3 = Ho[row * 132 + lane + 96];
            float sum = v0 + v1 + v2 + v3;
            float sq  = v0 * v0 + v1 * v1 + v2 * v2 + v3 * v3;
            #pragma unroll
            for (int off = 16; off > 0; off >>= 1) {
                sum += __shfl_xor_sync(0xffffffffu, sum, off);
                sq  += __shfl_xor_sync(0xffffffffu, sq,  off);
            }
            float mu  = sum * (1.0f / 128.0f);
            float var = sq * (1.0f / 128.0f) - mu * mu;
            float rs  = rsqrtf(var + 1e-5f);
            int eg = e0 + row;
            if (eg < EDGES) {
                float* o = out + (size_t)eg * DD;
                o[lane]      = (v0 - mu) * rs * g0 + b0;
                o[lane + 32] = (v1 - mu) * rs * g1 + b1;
                o[lane + 64] = (v2 - mu) * rs * g2 + b2;
                o[lane + 96] = (v3 - mu) * rs * g3 + b3;
            }
        }
    }
}

extern "C" void kernel_launch(void* const* d_in, const int* in_sizes, int n_in,
                              void* d_out, int out_size) {
    const float* node_attr = (const float*)d_in[0];
    const void*  eidx      = d_in[1];
    const float* edge_attr = (const float*)d_in[2];
    const float* W1        = (const float*)d_in[3];
    const float* b1        = (const float*)d_in[4];
    const float* W2        = (const float*)d_in[5];
    const float* b2        = (const float*)d_in[6];
    const float* gamma_    = (const float*)d_in[7];
    const float* beta_     = (const float*)d_in[8];

    cudaFuncSetAttribute(edge_mlp_mma, cudaFuncAttributeMaxDynamicSharedMemorySize, SMEM_ALLOC);

    prep_w_kernel<<<96, 256>>>(W1, W2);
    edge_mlp_mma<<<NCTA, NT, SMEM_ALLOC>>>(node_attr, eidx, edge_attr,
                                           b1, b2, gamma_, beta_, (float*)d_out);
}

// round 7
// speedup vs baseline: 1.7446x; 1.0644x over previous
#include <cuda_runtime.h>
#include <cstdint>

#define EDGES 625000
#define DD    128
#define BE    128
#define NT    512
#define NCTA  ((EDGES + BE - 1) / BE)   // 4883

// ---------------- smem layout (bytes) ----------------
// A chunk (k64, fp16 natural+swizzle): 128 rows x 128B = 16384 ; x2
// B chunk (k64, frag-direct):          4 ks x 16 nt x 256B = 16384 ; x2
// H (fp16 natural+swizzle):            128 rows x 256B = 32768
#define SM_A0   0
#define SM_A1   16384
#define SM_B0   32768
#define SM_B1   49152
#define SM_H    65536
#define SM_PART 98304          // 128 rows x 4 warps x float2 = 4096
#define SM_P    102400
#define P_B1    (SM_P + 0)
#define P_B2    (SM_P + 512)
#define P_G     (SM_P + 1024)
#define P_BT    (SM_P + 1536)
#define P_SEND  (SM_P + 2048)
#define P_RECV  (SM_P + 2560)
#define SMEM_ALLOC 106496

// weights in fp16 m16n8k16 B-fragment layout (verified in R6):
// block(kstep16, ntile8) = 256B: uint32 slot = lane*2 + r ; lane=(g<<2)|t
//   slot lo/hi = W[k][n], W[k+1][n]  with k = ks*16 + r*8 + t*2 , n = nt*8 + g
__device__ __align__(16) uint32_t g_W1F[24 * 16 * 64];
__device__ __align__(16) uint32_t g_W2F[8 * 16 * 64];

__device__ __forceinline__ uint32_t packf16(float lo, float hi) {
    uint32_t u;
    asm("cvt.rn.f16x2.f32 %0, %1, %2;" : "=r"(u) : "f"(hi), "f"(lo));
    return u;
}

__global__ void prep_w_kernel(const float* __restrict__ W1,
                              const float* __restrict__ W2) {
    int i = blockIdx.x * 256 + threadIdx.x;
    if (i < 24 * 16 * 64) {
        int blk = i >> 6, w = i & 63;
        int lane = w >> 1, r = w & 1;
        int g = lane >> 2, t = lane & 3;
        int ks = blk >> 4, nt = blk & 15;
        int k = ks * 16 + r * 8 + t * 2;
        int n = nt * 8 + g;
        g_W1F[i] = packf16(W1[k * 128 + n], W1[(k + 1) * 128 + n]);
    }
    if (i < 8 * 16 * 64) {
        int blk = i >> 6, w = i & 63;
        int lane = w >> 1, r = w & 1;
        int g = lane >> 2, t = lane & 3;
        int ks = blk >> 4, nt = blk & 15;
        int k = ks * 16 + r * 8 + t * 2;
        int n = nt * 8 + g;
        g_W2F[i] = packf16(W2[k * 128 + n], W2[(k + 1) * 128 + n]);
    }
}

__device__ __forceinline__ void mma_fp16(float& c0, float& c1, float& c2, float& c3,
                                         uint32_t a0, uint32_t a1, uint32_t a2, uint32_t a3,
                                         uint32_t b0, uint32_t b1) {
    asm volatile("mma.sync.aligned.m16n8k16.row.col.f32.f16.f16.f32 "
                 "{%0,%1,%2,%3}, {%4,%5,%6,%7}, {%8,%9}, {%0,%1,%2,%3};"
                 : "+f"(c0), "+f"(c1), "+f"(c2), "+f"(c3)
                 : "r"(a0), "r"(a1), "r"(a2), "r"(a3), "r"(b0), "r"(b1));
}

__device__ __forceinline__ void ldsm4(uint32_t& r0, uint32_t& r1, uint32_t& r2, uint32_t& r3,
                                      uint32_t addr) {
    asm volatile("ldmatrix.sync.aligned.m8n8.x4.shared.b16 {%0,%1,%2,%3}, [%4];"
                 : "=r"(r0), "=r"(r1), "=r"(r2), "=r"(r3) : "r"(addr));
}

__device__ __forceinline__ void cp16(uint32_t saddr, const void* gptr) {
    asm volatile("cp.async.cg.shared.global [%0], [%1], 16;"
                 :: "r"(saddr), "l"(gptr));
}
#define CP_COMMIT() asm volatile("cp.async.commit_group;" ::: "memory")
#define CP_WAIT(n)  asm volatile("cp.async.wait_group %0;" :: "n"(n) : "memory")

__global__ __launch_bounds__(NT, 1) void edge_mlp_mma(
    const float* __restrict__ node_attr,
    const void*  __restrict__ eidx_raw,
    const float* __restrict__ edge_attr,
    const float* __restrict__ b1g,
    const float* __restrict__ b2g,
    const float* __restrict__ gg,
    const float* __restrict__ btg,
    float* __restrict__ out)
{
    extern __shared__ char smem[];
    uint32_t smb;
    asm("{ .reg .u64 t; cvta.to.shared.u64 t, %1; cvt.u32.u64 %0, t; }"
        : "=r"(smb) : "l"(smem));

    const int tid   = threadIdx.x;
    const int wid   = tid >> 5;
    const int lane  = tid & 31;
    const int g     = lane >> 2;
    const int t     = lane & 3;
    const int wm    = wid >> 2;    // 0..3 (M quarter, 32 rows)
    const int wn    = wid & 3;     // 0..3 (N quarter, 32 cols)
    const int e0    = blockIdx.x * BE;
    const int lrow7 = lane & 7;                              // ldmatrix row-within-8
    const int rowb  = wm * 32 + lrow7 + 8 * ((lane >> 3) & 1); // ldmatrix base row
    const int grx   = (lane >> 4) & 1;                       // k-half granule

    if (tid < 128) {
        ((float*)(smem + P_B1))[tid] = b1g[tid];
        ((float*)(smem + P_B2))[tid] = b2g[tid];
        ((float*)(smem + P_G ))[tid] = gg[tid];
        ((float*)(smem + P_BT))[tid] = btg[tid];
    }
    const int* raw32 = (const int*)eidx_raw;
    bool is64 = true;
    #pragma unroll
    for (int i = 0; i < 16; i++) is64 &= (raw32[2 * i + 1] == 0);
    if (tid < BE) {
        int eg = e0 + tid; if (eg >= EDGES) eg = EDGES - 1;
        int s, r;
        if (is64) { const long long* p = (const long long*)eidx_raw;
                    s = (int)p[eg]; r = (int)p[EDGES + eg]; }
        else      { s = raw32[eg]; r = raw32[EDGES + eg]; }
        ((int*)(smem + P_SEND))[tid] = s;
        ((int*)(smem + P_RECV))[tid] = r;
    }

    const uint32_t bbuf[2] = {smb + SM_B0, smb + SM_B1};

    // issue B chunk 0 of GEMM1 (16KB)
    #pragma unroll
    for (int it = 0; it < 2; it++) {
        int idx = tid + it * NT;
        cp16(bbuf[0] + idx * 16, g_W1F + idx * 4);
    }
    CP_COMMIT();
    __syncthreads();   // send/recv visible

    const int* sSend = (const int*)(smem + P_SEND);
    const int* sRecv = (const int*)(smem + P_RECV);

    // prefetch A chunk 0 (sender, k 0..63): 2048 float4 slots
    float4 prA[4];
    #pragma unroll
    for (int it = 0; it < 4; it++) {
        int idx = tid + it * NT;
        int row = idx >> 4, jc = idx & 15;
        prA[it] = *(const float4*)(node_attr + (size_t)sSend[row] * DD + jc * 4);
    }

    float acc[2][4][4];
    #pragma unroll
    for (int i = 0; i < 2; i++)
        #pragma unroll
        for (int j = 0; j < 4; j++)
            #pragma unroll
            for (int r = 0; r < 4; r++) acc[i][j][r] = 0.0f;

    // =================== GEMM1: 6 chunks of k=64 ===================
    #pragma unroll 1
    for (int c = 0; c < 6; c++) {
        const uint32_t aoff = (c & 1) ? SM_A1 : SM_A0;
        char* abuf = smem + aoff;
        // scatter A(c): natural row-major fp16, XOR-swizzled, STS.64 conflict-free
        #pragma unroll
        for (int it = 0; it < 4; it++) {
            int idx = tid + it * NT;
            int row = idx >> 4, jc = idx & 15;
            int sw = (jc >> 1) ^ (row & 7);
            uint2 v;
            v.x = packf16(prA[it].x, prA[it].y);
            v.y = packf16(prA[it].z, prA[it].w);
            *(uint2*)(abuf + row * 128 + sw * 16 + (jc & 1) * 8) = v;
        }
        CP_WAIT(0);              // B(c) landed
        __syncthreads();         // A(c) visible; MMA(c-1) done by all warps

        if (c < 5) {
            int cn = c + 1;
            #pragma unroll
            for (int it = 0; it < 2; it++) {
                int idx = tid + it * NT;
                cp16(bbuf[cn & 1] + idx * 16, g_W1F + cn * 4096 + idx * 4);
            }
            CP_COMMIT();
            #pragma unroll
            for (int it = 0; it < 4; it++) {
                int idx = tid + it * NT;
                int row = idx >> 4, jc = idx & 15;
                const float* src;
                if (cn < 2)      src = node_attr + (size_t)sSend[row] * DD + cn * 64;
                else if (cn < 4) src = node_attr + (size_t)sRecv[row] * DD + (cn - 2) * 64;
                else { int eg = e0 + row; if (eg >= EDGES) eg = EDGES - 1;
                       src = edge_attr + (size_t)eg * DD + (cn - 4) * 64; }
                prA[it] = *(const float4*)(src + jc * 4);
            }
        }

        const char* bb = smem + (SM_B0 + (c & 1) * 16384);
        const uint32_t abase = smb + aoff;
        #pragma unroll
        for (int s = 0; s < 4; s++) {
            uint2 b[4];
            #pragma unroll
            for (int j = 0; j < 4; j++)
                b[j] = *(const uint2*)(bb + ((s * 16) + wn * 4 + j) * 256 + lane * 8);
            #pragma unroll
            for (int i = 0; i < 2; i++) {
                uint32_t a0, a1, a2, a3;
                uint32_t ad = abase + (rowb + i * 16) * 128 +
                              (((s * 2 + grx) ^ lrow7) << 4);
                ldsm4(a0, a1, a2, a3, ad);
                #pragma unroll
                for (int j = 0; j < 4; j++)
                    mma_fp16(acc[i][j][0], acc[i][j][1], acc[i][j][2], acc[i][j][3],
                             a0, a1, a2, a3, b[j].x, b[j].y);
            }
        }
    }

    // issue GEMM2 B chunk 0 into buf0 (last read was MMA chunk 4 -> safe)
    #pragma unroll
    for (int it = 0; it < 2; it++) {
        int idx = tid + it * NT;
        cp16(bbuf[0] + idx * 16, g_W2F + idx * 4);
    }
    CP_COMMIT();

    // ========== epilogue1: bias + ReLU -> H (natural fp16, swizzled) ==========
    {
        const float* B1 = (const float*)(smem + P_B1);
        #pragma unroll
        for (int i = 0; i < 2; i++) {
            int row_lo = wm * 32 + i * 16 + g;    // row&7 = g
            #pragma unroll
            for (int j = 0; j < 4; j++) {
                int col = wn * 32 + j * 8 + 2 * t;
                float x0 = fmaxf(acc[i][j][0] + B1[col],     0.0f);
                float x1 = fmaxf(acc[i][j][1] + B1[col + 1], 0.0f);
                float x2 = fmaxf(acc[i][j][2] + B1[col],     0.0f);
                float x3 = fmaxf(acc[i][j][3] + B1[col + 1], 0.0f);
                int swg = ((wn * 4 + j) ^ g) * 16 + 4 * t;
                *(uint32_t*)(smem + SM_H + row_lo * 256 + swg)       = packf16(x0, x1);
                *(uint32_t*)(smem + SM_H + (row_lo + 8) * 256 + swg) = packf16(x2, x3);
                acc[i][j][0] = 0.0f; acc[i][j][1] = 0.0f;
                acc[i][j][2] = 0.0f; acc[i][j][3] = 0.0f;
            }
        }
    }
    __syncthreads();   // H visible; MMA1(5) done -> buf1 free

    // issue GEMM2 B chunk 1 into buf1
    #pragma unroll
    for (int it = 0; it < 2; it++) {
        int idx = tid + it * NT;
        cp16(bbuf[1] + idx * 16, g_W2F + 4096 + idx * 4);
    }
    CP_COMMIT();
    CP_WAIT(1);        // B2(0) done, B2(1) in flight
    __syncthreads();

    // =================== GEMM2: 2 chunks of k=64, A via LDSM from H ===================
    #pragma unroll 1
    for (int c = 0; c < 2; c++) {
        if (c == 1) { CP_WAIT(0); __syncthreads(); }
        const char* bb = smem + (SM_B0 + c * 16384);
        #pragma unroll
        for (int s = 0; s < 4; s++) {
            uint2 b[4];
            #pragma unroll
            for (int j = 0; j < 4; j++)
                b[j] = *(const uint2*)(bb + ((s * 16) + wn * 4 + j) * 256 + lane * 8);
            #pragma unroll
            for (int i = 0; i < 2; i++) {
                uint32_t a0, a1, a2, a3;
                uint32_t ad = smb + SM_H + (rowb + i * 16) * 256 +
                              (((c * 8 + s * 2 + grx) ^ lrow7) << 4);
                ldsm4(a0, a1, a2, a3, ad);
                #pragma unroll
                for (int j = 0; j < 4; j++)
                    mma_fp16(acc[i][j][0], acc[i][j][1], acc[i][j][2], acc[i][j][3],
                             a0, a1, a2, a3, b[j].x, b[j].y);
            }
        }
    }

    // ========== bias2 + LayerNorm from registers ==========
    {
        const float* B2 = (const float*)(smem + P_B2);
        // bias add in regs
        #pragma unroll
        for (int i = 0; i < 2; i++)
            #pragma unroll
            for (int j = 0; j < 4; j++) {
                int col = wn * 32 + j * 8 + 2 * t;
                acc[i][j][0] += B2[col];     acc[i][j][1] += B2[col + 1];
                acc[i][j][2] += B2[col];     acc[i][j][3] += B2[col + 1];
            }
        // per-row partials over this warp's 32 cols (reduce across 4 t-lanes)
        float2* part = (float2*)(smem + SM_PART);   // [row][wn]
        #pragma unroll
        for (int i = 0; i < 2; i++)
            #pragma unroll
            for (int hi = 0; hi < 2; hi++) {
                float s = 0.0f, q = 0.0f;
                #pragma unroll
                for (int j = 0; j < 4; j++) {
                    float v0 = acc[i][j][hi * 2], v1 = acc[i][j][hi * 2 + 1];
                    s += v0 + v1; q += v0 * v0 + v1 * v1;
                }
                s += __shfl_xor_sync(0xffffffffu, s, 1);
                q += __shfl_xor_sync(0xffffffffu, q, 1);
                s += __shfl_xor_sync(0xffffffffu, s, 2);
                q += __shfl_xor_sync(0xffffffffu, q, 2);
                if (t == 0) {
                    int row = wm * 32 + i * 16 + g + 8 * hi;
                    part[row * 4 + wn] = make_float2(s, q);
                }
            }
    }
    __syncthreads();

    {
        const float* G  = (const float*)(smem + P_G);
        const float* Bt = (const float*)(smem + P_BT);
        const float2* part = (const float2*)(smem + SM_PART);
        #pragma unroll
        for (int i = 0; i < 2; i++)
            #pragma unroll
            for (int hi = 0; hi < 2; hi++) {
                int row = wm * 32 + i * 16 + g + 8 * hi;
                float2 p0 = part[row * 4 + 0], p1 = part[row * 4 + 1];
                float2 p2 = part[row * 4 + 2], p3 = part[row * 4 + 3];
                float sum = p0.x + p1.x + p2.x + p3.x;
                float sq  = p0.y + p1.y + p2.y + p3.y;
                float mu  = sum * (1.0f / 128.0f);
                float var = sq * (1.0f / 128.0f) - mu * mu;
                float rs  = rsqrtf(var + 1e-5f);
                int eg = e0 + row;
                if (eg < EDGES) {
                    float* o = out + (size_t)eg * DD;
                    #pragma unroll
                    for (int j = 0; j < 4; j++) {
                        int col = wn * 32 + j * 8 + 2 * t;
                        float2 v;
                        v.x = (acc[i][j][hi * 2]     - mu) * rs * G[col]     + Bt[col];
                        v.y = (acc[i][j][hi * 2 + 1] - mu) * rs * G[col + 1] + Bt[col + 1];
                        *(float2*)(o + col) = v;
                    }
                }
            }
    }
}

extern "C" void kernel_launch(void* const* d_in, const int* in_sizes, int n_in,
                              void* d_out, int out_size) {
    const float* node_attr = (const float*)d_in[0];
    const void*  eidx      = d_in[1];
    const float* edge_attr = (const float*)d_in[2];
    const float* W1        = (const float*)d_in[3];
    const float* b1        = (const float*)d_in[4];
    const float* W2        = (const float*)d_in[5];
    const float* b2        = (const float*)d_in[6];
    const float* gamma_    = (const float*)d_in[7];
    const float* beta_     = (const float*)d_in[8];

    cudaFuncSetAttribute(edge_mlp_mma, cudaFuncAttributeMaxDynamicSharedMemorySize, SMEM_ALLOC);

    prep_w_kernel<<<96, 256>>>(W1, W2);
    edge_mlp_mma<<<NCTA, NT, SMEM_ALLOC>>>(node_attr, eidx, edge_attr,
                                           b1, b2, gamma_, beta_, (float*)d_out);
}